// round 15
// baseline (speedup 1.0000x reference)
#include <cuda_runtime.h>
#include <cuda_bf16.h>
#include <math.h>
#include <stdint.h>

// Problem constants
#define B_DIM  64
#define T_DIM  256
#define D_DIM  768
#define NH_DIM 12
#define DH_DIM 64
#define C_DIM  7
#define M_ROWS (B_DIM * T_DIM)   // 16384
#define NQKV   (3 * D_DIM)       // 2304
#define KB16   (D_DIM / 16)      // 48
#define MB16   (M_ROWS / 16)     // 1024
#define NB8    (NQKV / 8)        // 288

// Prep-kernel block ranges
#define PA_BLOCKS  (MB16 * KB16 * 32 / 256)   // 6144
#define PW_BLOCKS  (NB8  * KB16 * 32 / 256)   // 1728
#define WC_BLOCKS  24
#define PREP_BLOCKS (PA_BLOCKS + PW_BLOCKS + WC_BLOCKS)

// GEMM + fused H-classifier grid
#define GEMM_BLOCKS   (18 * 128)              // 2304
#define HCLS_BLOCKS   (M_ROWS / 32)           // 512  (8 warps x 4 rows)
#define GEMMH_BLOCKS  (GEMM_BLOCKS + HCLS_BLOCKS)

// ---------------------------------------------------------------------------
// Scratch (device globals; no runtime allocation allowed)
// ---------------------------------------------------------------------------
__device__ __nv_bfloat16 g_Q[(size_t)M_ROWS * D_DIM];
__device__ __nv_bfloat16 g_K[(size_t)M_ROWS * D_DIM];
__device__ __nv_bfloat16 g_V[(size_t)M_ROWS * D_DIM];
__device__ __nv_bfloat16 g_CTX[(size_t)M_ROWS * D_DIM];
__device__ __nv_bfloat16 g_Abf[(size_t)MB16 * KB16 * 256];
__device__ __nv_bfloat16 g_Wbf[(size_t)NB8  * KB16 * 128];
__device__ float g_bpack[NQKV];
__device__ float g_WoWc[D_DIM * C_DIM];
__device__ float g_boWc[C_DIM];

// ---------------------------------------------------------------------------
__device__ __forceinline__ uint32_t pack_bf2(float lo, float hi) {
    __nv_bfloat162 t = __floats2bfloat162_rn(lo, hi);
    return *reinterpret_cast<uint32_t*>(&t);
}

// ---------------------------------------------------------------------------
// Fused prep: pack A fragments | pack W fragments + biases | WoWc fold.
// (proven)
// ---------------------------------------------------------------------------
__global__ __launch_bounds__(256)
void prep_kernel(const float* __restrict__ H,
                 const float* __restrict__ Wq, const float* __restrict__ Wk,
                 const float* __restrict__ Wv,
                 const float* __restrict__ bq, const float* __restrict__ bk,
                 const float* __restrict__ bv,
                 const float* __restrict__ Wo, const float* __restrict__ Wc,
                 const float* __restrict__ bo,
                 __nv_bfloat16* __restrict__ Abf,
                 __nv_bfloat16* __restrict__ Wbf,
                 float* __restrict__ bp,
                 float* __restrict__ WoWc, float* __restrict__ boWc)
{
    const int blk = blockIdx.x;

    if (blk < PA_BLOCKS) {
        const int idx  = blk * 256 + threadIdx.x;
        const int lane = idx & 31;
        const int kblk = (idx >> 5) % KB16;
        const int mblk = idx / (KB16 * 32);
        const int gid  = lane >> 2;
        const int tig  = lane & 3;
        const int m0 = mblk * 16 + gid;
        const int k0 = kblk * 16 + 2 * tig;

        float2 p00 = *(const float2*)&H[(size_t)m0 * D_DIM + k0];
        float2 p10 = *(const float2*)&H[(size_t)(m0 + 8) * D_DIM + k0];
        float2 p01 = *(const float2*)&H[(size_t)m0 * D_DIM + k0 + 8];
        float2 p11 = *(const float2*)&H[(size_t)(m0 + 8) * D_DIM + k0 + 8];

        uint4 out;
        out.x = pack_bf2(p00.x, p00.y);
        out.y = pack_bf2(p10.x, p10.y);
        out.z = pack_bf2(p01.x, p01.y);
        out.w = pack_bf2(p11.x, p11.y);
        *(uint4*)&Abf[(size_t)idx * 8] = out;

    } else if (blk < PA_BLOCKS + PW_BLOCKS) {
        const int idx  = (blk - PA_BLOCKS) * 256 + threadIdx.x;
        const int lane = idx & 31;
        const int kblk = (idx >> 5) % KB16;
        const int nblk = idx / (KB16 * 32);
        const int gid  = lane >> 2;
        const int tig  = lane & 3;
        const int n  = nblk * 8 + gid;
        const int k0 = kblk * 16 + 2 * tig;

        const float* W = (n < D_DIM) ? Wq : ((n < 2 * D_DIM) ? Wk : Wv);
        const int j = (n >= 2 * D_DIM) ? (n - 2 * D_DIM)
                     : ((n >= D_DIM) ? (n - D_DIM) : n);

        const float w0 = W[(size_t)k0 * D_DIM + j];
        const float w1 = W[(size_t)(k0 + 1) * D_DIM + j];
        const float w2 = W[(size_t)(k0 + 8) * D_DIM + j];
        const float w3 = W[(size_t)(k0 + 9) * D_DIM + j];

        uint2 out;
        out.x = pack_bf2(w0, w1);
        out.y = pack_bf2(w2, w3);
        *(uint2*)&Wbf[(size_t)idx * 4] = out;

        if (idx < NQKV) {
            float bv_;
            if (idx < D_DIM)            bv_ = bq[idx];
            else if (idx < 2 * D_DIM)   bv_ = bk[idx - D_DIM];
            else                        bv_ = bv[idx - 2 * D_DIM];
            bp[idx] = bv_;
        }

    } else {
        const int wblk   = blk - PA_BLOCKS - PW_BLOCKS;
        const int gwarp  = (wblk * 256 + threadIdx.x) >> 5;
        const int nwarps = (WC_BLOCKS * 256) >> 5;
        const int lane   = threadIdx.x & 31;

        for (int d = gwarp; d < D_DIM; d += nwarps) {
            float acc[C_DIM];
            #pragma unroll
            for (int c = 0; c < C_DIM; c++) acc[c] = 0.0f;
            for (int n = lane; n < D_DIM; n += 32) {
                const float w = Wo[(size_t)d * D_DIM + n];
                const float* wcr = &Wc[(size_t)(D_DIM + n) * C_DIM];
                #pragma unroll
                for (int c = 0; c < C_DIM; c++) acc[c] += w * wcr[c];
            }
            #pragma unroll
            for (int c = 0; c < C_DIM; c++) {
                acc[c] += __shfl_xor_sync(0xFFFFFFFFu, acc[c], 16);
                acc[c] += __shfl_xor_sync(0xFFFFFFFFu, acc[c], 8);
                acc[c] += __shfl_xor_sync(0xFFFFFFFFu, acc[c], 4);
                acc[c] += __shfl_xor_sync(0xFFFFFFFFu, acc[c], 2);
                acc[c] += __shfl_xor_sync(0xFFFFFFFFu, acc[c], 1);
            }
            if (lane == 0) {
                #pragma unroll
                for (int c = 0; c < C_DIM; c++) WoWc[d * C_DIM + c] = acc[c];
            }
        }

        const int g = wblk * 256 + threadIdx.x;
        if (g < C_DIM) {
            float a = 0.0f;
            for (int n = 0; n < D_DIM; n++)
                a += bo[n] * Wc[(size_t)(D_DIM + n) * C_DIM + g];
            boWc[g] = a;
        }
    }
}

// ---------------------------------------------------------------------------
// BF16 tensor-core GEMM (proven) + fused H-classifier tail blocks.
// GEMM blocks: blk < GEMM_BLOCKS (bx = blk%18, by = blk/18).
// H-classifier blocks: 8 warps x 4 rows each; out_all = H @ Wc_top + bc.
// ---------------------------------------------------------------------------
#define A_STAGE_H 8192
#define B_STAGE_H 8192
#define GEMM_SMEM_BYTES (3 * (A_STAGE_H + B_STAGE_H) * 2)  // 98304
#define WPAD 772

__device__ __forceinline__ void cp_async16(uint32_t smem_addr, const void* gptr) {
    asm volatile("cp.async.cg.shared.global [%0], [%1], 16;\n"
                 :: "r"(smem_addr), "l"(gptr));
}

__device__ __forceinline__ void mma_bf16_r(float* d,
                                           uint32_t a0, uint32_t a1,
                                           uint32_t a2, uint32_t a3,
                                           uint32_t b0, uint32_t b1) {
    asm volatile(
        "mma.sync.aligned.m16n8k16.row.col.f32.bf16.bf16.f32 "
        "{%0,%1,%2,%3}, {%4,%5,%6,%7}, {%8,%9}, {%0,%1,%2,%3};\n"
        : "+f"(d[0]), "+f"(d[1]), "+f"(d[2]), "+f"(d[3])
        : "r"(a0), "r"(a1), "r"(a2), "r"(a3), "r"(b0), "r"(b1));
}

__global__ __launch_bounds__(256, 2)
void bf16_gemm_kernel(const __nv_bfloat16* __restrict__ Abf,
                      const __nv_bfloat16* __restrict__ Wbf,
                      const float* __restrict__ bias,
                      __nv_bfloat16* __restrict__ C0,
                      __nv_bfloat16* __restrict__ C1,
                      __nv_bfloat16* __restrict__ C2,
                      const float* __restrict__ H,
                      const float* __restrict__ Wc,
                      const float* __restrict__ bc,
                      float* __restrict__ out_all)
{
    extern __shared__ __nv_bfloat16 smem[];
    const int tid  = threadIdx.x;
    const int lane = tid & 31;
    const int warp = tid >> 5;

    if (blockIdx.x >= GEMM_BLOCKS) {
        // ================= H-classifier block =================
        float* Wtop = (float*)smem;   // [C][WPAD]
        for (int i = tid; i < D_DIM * C_DIM; i += 256) {
            const int dd = i / C_DIM, cc = i % C_DIM;
            Wtop[cc * WPAD + dd] = Wc[i];
        }
        __syncthreads();

        const int hb   = blockIdx.x - GEMM_BLOCKS;       // 0..511
        const int row0 = hb * 32 + warp * 4;

        float acc[4][C_DIM];
        #pragma unroll
        for (int r = 0; r < 4; r++)
            #pragma unroll
            for (int c = 0; c < C_DIM; c++) acc[r][c] = 0.0f;

        #pragma unroll
        for (int i = 0; i < 6; i++) {
            const int off = (i * 32 + lane) * 4;
            float4 h4[4];
            #pragma unroll
            for (int r = 0; r < 4; r++)
                h4[r] = *(const float4*)&H[(size_t)(row0 + r) * D_DIM + off];
            #pragma unroll
            for (int c = 0; c < C_DIM; c++) {
                const float4 w = *(const float4*)&Wtop[c * WPAD + off];
                #pragma unroll
                for (int r = 0; r < 4; r++)
                    acc[r][c] += h4[r].x * w.x + h4[r].y * w.y
                               + h4[r].z * w.z + h4[r].w * w.w;
            }
        }

        #pragma unroll
        for (int r = 0; r < 4; r++)
            #pragma unroll
            for (int c = 0; c < C_DIM; c++) {
                acc[r][c] += __shfl_xor_sync(0xFFFFFFFFu, acc[r][c], 16);
                acc[r][c] += __shfl_xor_sync(0xFFFFFFFFu, acc[r][c], 8);
                acc[r][c] += __shfl_xor_sync(0xFFFFFFFFu, acc[r][c], 4);
                acc[r][c] += __shfl_xor_sync(0xFFFFFFFFu, acc[r][c], 2);
                acc[r][c] += __shfl_xor_sync(0xFFFFFFFFu, acc[r][c], 1);
            }

        if (lane == 0) {
            #pragma unroll
            for (int r = 0; r < 4; r++) {
                float* o = &out_all[(size_t)(row0 + r) * C_DIM];
                #pragma unroll
                for (int c = 0; c < C_DIM; c++) o[c] = acc[r][c] + bc[c];
            }
        }
        return;
    }

    // ================= GEMM block (proven round-10 core) =================
    __nv_bfloat16* As = smem;
    __nv_bfloat16* Bs = smem + 3 * A_STAGE_H;

    const int bx = blockIdx.x % 18;
    const int by = blockIdx.x / 18;
    const int gid  = lane >> 2;
    const int tig  = lane & 3;

    const int mrow0 = by * 8;
    const int nb0   = bx * 16;
    const int block_row = by * 128;
    const int block_col = bx * 128;

    const int seg = block_col / D_DIM;
    __nv_bfloat16* Cout = (seg == 0) ? C0 : (seg == 1 ? C1 : C2);
    const int out_col_base = block_col - seg * D_DIM;

    const uint32_t As_u32 = (uint32_t)__cvta_generic_to_shared(As);
    const uint32_t Bs_u32 = As_u32 + 3 * A_STAGE_H * 2;

    float d[2][8][4];
    #pragma unroll
    for (int mi = 0; mi < 2; mi++)
        #pragma unroll
        for (int ni = 0; ni < 8; ni++)
            #pragma unroll
            for (int e = 0; e < 4; e++)
                d[mi][ni][e] = 0.0f;

    const int NITER = KB16 / 4;   // 12

    auto do_stage = [&](int kb0, int s) {
        #pragma unroll
        for (int si = 0; si < 4; si++) {
            const int c   = tid + si * 256;
            const int mb  = c >> 7;
            const int kbl = (c >> 5) & 3;
            const int ch  = c & 31;
            cp_async16(As_u32 + (s * A_STAGE_H + c * 8) * 2,
                       Abf + (((size_t)(mrow0 + mb) * KB16 + kb0 + kbl) << 8) + ch * 8);
        }
        #pragma unroll
        for (int si = 0; si < 4; si++) {
            const int c   = tid + si * 256;
            const int nb  = c >> 6;
            const int kbl = (c >> 4) & 3;
            const int ch  = c & 15;
            cp_async16(Bs_u32 + (s * B_STAGE_H + c * 8) * 2,
                       Wbf + (((size_t)(nb0 + nb) * KB16 + kb0 + kbl) << 7) + ch * 8);
        }
        asm volatile("cp.async.commit_group;\n");
    };

    do_stage(0, 0);
    do_stage(4, 1);

    const int warp_mb = (warp & 3) * 2;
    const int warp_nb = (warp >> 2) * 8;

    for (int it = 0; it < NITER; it++) {
        if (it + 1 < NITER) asm volatile("cp.async.wait_group 1;\n");
        else                asm volatile("cp.async.wait_group 0;\n");
        __syncthreads();

        if (it + 2 < NITER) do_stage((it + 2) * 4, (it + 2) % 3);

        const int s = it % 3;
        const uint4* As4 = (const uint4*)As + s * (A_STAGE_H / 8);
        const uint2* Bs2 = (const uint2*)Bs + s * (B_STAGE_H / 4);

        #pragma unroll
        for (int kb = 0; kb < 4; kb++) {
            uint4 afr[2];
            #pragma unroll
            for (int mi = 0; mi < 2; mi++)
                afr[mi] = As4[((warp_mb + mi) * 4 + kb) * 32 + lane];
            uint2 bfr[8];
            #pragma unroll
            for (int ni = 0; ni < 8; ni++)
                bfr[ni] = Bs2[((warp_nb + ni) * 4 + kb) * 32 + lane];
            #pragma unroll
            for (int mi = 0; mi < 2; mi++)
                #pragma unroll
                for (int ni = 0; ni < 8; ni++)
                    mma_bf16_r(d[mi][ni], afr[mi].x, afr[mi].y, afr[mi].z,
                               afr[mi].w, bfr[ni].x, bfr[ni].y);
        }
    }

    #pragma unroll
    for (int mi = 0; mi < 2; mi++) {
        const int r0 = block_row + (warp & 3) * 32 + mi * 16 + gid;
        const int r1 = r0 + 8;
        #pragma unroll
        for (int ni = 0; ni < 8; ni++) {
            const int cg = block_col + (warp >> 2) * 64 + ni * 8 + 2 * tig;
            const int cl = out_col_base + (warp >> 2) * 64 + ni * 8 + 2 * tig;
            const float b0 = bias[cg], b1 = bias[cg + 1];
            *(uint32_t*)&Cout[(size_t)r0 * D_DIM + cl] =
                pack_bf2(d[mi][ni][0] + b0, d[mi][ni][1] + b1);
            *(uint32_t*)&Cout[(size_t)r1 * D_DIM + cl] =
                pack_bf2(d[mi][ni][2] + b0, d[mi][ni][3] + b1);
        }
    }
}

// ---------------------------------------------------------------------------
// BF16 flash-attention v3 (round 13/14, proven): Q fragments in registers.
// ---------------------------------------------------------------------------
#define AQ_ST 72
#define AV_ST 264
#define ATT_SMEM_BYTES ((T_DIM * AQ_ST + DH_DIM * AV_ST) * 2)  // 70656

__global__ __launch_bounds__(512)
void flash_attn_kernel(const __nv_bfloat16* __restrict__ Q,
                       const __nv_bfloat16* __restrict__ K,
                       const __nv_bfloat16* __restrict__ V,
                       const int*   __restrict__ num_turns,
                       __nv_bfloat16* __restrict__ CTX)
{
    const int b = blockIdx.x / NH_DIM;
    const int h = blockIdx.x % NH_DIM;

    extern __shared__ __nv_bfloat16 asm_[];
    __nv_bfloat16* Ks = asm_;
    __nv_bfloat16* Vt = Ks + T_DIM * AQ_ST;

    const size_t base = ((size_t)b * T_DIM * NH_DIM + h) * DH_DIM;
    const int tid = threadIdx.x;

    for (int idx = tid; idx < T_DIM * 8; idx += 512) {
        const int t  = idx >> 3;
        const int c8 = (idx & 7) * 8;
        *(uint4*)&Ks[t * AQ_ST + c8] =
            *(const uint4*)&K[base + (size_t)t * D_DIM + c8];
    }
    for (int idx = tid; idx < (T_DIM / 2) * 8; idx += 512) {
        const int tp = idx >> 3;
        const int c8 = (idx & 7) * 8;
        const int t0 = tp * 2;
        const uint4 v0 = *(const uint4*)&V[base + (size_t)t0 * D_DIM + c8];
        const uint4 v1 = *(const uint4*)&V[base + (size_t)(t0 + 1) * D_DIM + c8];
        const uint16_t* h0 = reinterpret_cast<const uint16_t*>(&v0);
        const uint16_t* h1 = reinterpret_cast<const uint16_t*>(&v1);
        #pragma unroll
        for (int j = 0; j < 8; j++) {
            const uint32_t pr = (uint32_t)h0[j] | ((uint32_t)h1[j] << 16);
            *(uint32_t*)&Vt[(c8 + j) * AV_ST + t0] = pr;
        }
    }

    const int warp = tid >> 5;
    const int lane = tid & 31;
    const int gid  = lane >> 2;
    const int tig  = lane & 3;

    const int q0 = warp * 16 + gid;
    const int q1 = q0 + 8;
    const int ntv  = num_turns[b];
    const int lim0 = min(q0, ntv);
    const int lim1 = min(q1, ntv);

    uint32_t qfr[4][4];
    {
        const __nv_bfloat16* qr0 = &Q[base + (size_t)q0 * D_DIM];
        const __nv_bfloat16* qr1 = &Q[base + (size_t)q1 * D_DIM];
        #pragma unroll
        for (int kt = 0; kt < 4; kt++) {
            const int dh = kt * 16;
            qfr[kt][0] = *(const uint32_t*)&qr0[dh + 2 * tig];
            qfr[kt][1] = *(const uint32_t*)&qr1[dh + 2 * tig];
            qfr[kt][2] = *(const uint32_t*)&qr0[dh + 8 + 2 * tig];
            qfr[kt][3] = *(const uint32_t*)&qr1[dh + 8 + 2 * tig];
        }
    }
    __syncthreads();

    const int lim_max = min(warp * 16 + 15, ntv);
    const int nch = (lim_max + 63) >> 6;

    float octx[8][4];
    #pragma unroll
    for (int i = 0; i < 8; i++)
        #pragma unroll
        for (int j = 0; j < 4; j++) octx[i][j] = 0.0f;
    float m0 = -1e30f, m1 = -1e30f, l0 = 0.0f, l1 = 0.0f;

    for (int ch = 0; ch < nch; ch++) {
        const int kbase = ch * 64;

        float s[8][4];
        #pragma unroll
        for (int i = 0; i < 8; i++)
            #pragma unroll
            for (int j = 0; j < 4; j++) s[i][j] = 0.0f;

        #pragma unroll
        for (int kt = 0; kt < 4; kt++) {
            const int dh = kt * 16;
            #pragma unroll
            for (int nt8 = 0; nt8 < 8; nt8++) {
                const int krow = kbase + nt8 * 8 + gid;
                const uint32_t b0 = *(const uint32_t*)&Ks[krow * AQ_ST + dh + 2 * tig];
                const uint32_t b1 = *(const uint32_t*)&Ks[krow * AQ_ST + dh + 8 + 2 * tig];
                mma_bf16_r(s[nt8], qfr[kt][0], qfr[kt][1], qfr[kt][2],
                           qfr[kt][3], b0, b1);
            }
        }

        float mx0 = -1e30f, mx1 = -1e30f;
        #pragma unroll
        for (int i = 0; i < 8; i++) {
            const int kc = kbase + i * 8 + 2 * tig;
            s[i][0] = (kc     < lim0) ? s[i][0] * 0.125f : -1e30f;
            s[i][1] = (kc + 1 < lim0) ? s[i][1] * 0.125f : -1e30f;
            s[i][2] = (kc     < lim1) ? s[i][2] * 0.125f : -1e30f;
            s[i][3] = (kc + 1 < lim1) ? s[i][3] * 0.125f : -1e30f;
            mx0 = fmaxf(mx0, fmaxf(s[i][0], s[i][1]));
            mx1 = fmaxf(mx1, fmaxf(s[i][2], s[i][3]));
        }
        mx0 = fmaxf(mx0, __shfl_xor_sync(0xFFFFFFFFu, mx0, 1));
        mx0 = fmaxf(mx0, __shfl_xor_sync(0xFFFFFFFFu, mx0, 2));
        mx1 = fmaxf(mx1, __shfl_xor_sync(0xFFFFFFFFu, mx1, 1));
        mx1 = fmaxf(mx1, __shfl_xor_sync(0xFFFFFFFFu, mx1, 2));

        const float nm0 = fmaxf(m0, mx0);
        const float nm1 = fmaxf(m1, mx1);
        const float corr0 = __expf(m0 - nm0);
        const float corr1 = __expf(m1 - nm1);
        m0 = nm0; m1 = nm1;
        l0 *= corr0; l1 *= corr1;
        #pragma unroll
        for (int i = 0; i < 8; i++) {
            octx[i][0] *= corr0; octx[i][1] *= corr0;
            octx[i][2] *= corr1; octx[i][3] *= corr1;
        }

        #pragma unroll
        for (int i = 0; i < 8; i++) {
            const float p0 = __expf(s[i][0] - m0);
            const float p1 = __expf(s[i][1] - m0);
            const float p2 = __expf(s[i][2] - m1);
            const float p3 = __expf(s[i][3] - m1);
            l0 += p0 + p1;  l1 += p2 + p3;
            s[i][0] = p0; s[i][1] = p1; s[i][2] = p2; s[i][3] = p3;
        }

        #pragma unroll
        for (int kt16 = 0; kt16 < 4; kt16++) {
            const int i0 = 2 * kt16, i1 = i0 + 1;
            const uint32_t a0 = pack_bf2(s[i0][0], s[i0][1]);
            const uint32_t a1 = pack_bf2(s[i0][2], s[i0][3]);
            const uint32_t a2 = pack_bf2(s[i1][0], s[i1][1]);
            const uint32_t a3 = pack_bf2(s[i1][2], s[i1][3]);
            const int kb = kbase + kt16 * 16;
            #pragma unroll
            for (int ndh = 0; ndh < 8; ndh++) {
                const int vrow = ndh * 8 + gid;
                const uint32_t b0 = *(const uint32_t*)&Vt[vrow * AV_ST + kb + 2 * tig];
                const uint32_t b1 = *(const uint32_t*)&Vt[vrow * AV_ST + kb + 8 + 2 * tig];
                mma_bf16_r(octx[ndh], a0, a1, a2, a3, b0, b1);
            }
        }
    }

    l0 += __shfl_xor_sync(0xFFFFFFFFu, l0, 1);
    l0 += __shfl_xor_sync(0xFFFFFFFFu, l0, 2);
    l1 += __shfl_xor_sync(0xFFFFFFFFu, l1, 1);
    l1 += __shfl_xor_sync(0xFFFFFFFFu, l1, 2);
    const float inv0 = (lim0 > 0) ? 1.0f / l0 : 0.0f;
    const float inv1 = (lim1 > 0) ? 1.0f / l1 : 0.0f;

    __nv_bfloat16* o0 = &CTX[base + (size_t)q0 * D_DIM];
    __nv_bfloat16* o1 = &CTX[base + (size_t)q1 * D_DIM];
    #pragma unroll
    for (int ndh = 0; ndh < 8; ndh++) {
        const int c = ndh * 8 + 2 * tig;
        *(uint32_t*)&o0[c] = pack_bf2(octx[ndh][0] * inv0, octx[ndh][1] * inv0);
        *(uint32_t*)&o1[c] = pack_bf2(octx[ndh][2] * inv1, octx[ndh][3] * inv1);
    }
}

// ---------------------------------------------------------------------------
// CTX-classifier: out_all += CTX @ WoWc + [t>0]*boWc; final gather.
// Warp per 4 rows (proven layout), transposed conflict-free smem weights.
// ---------------------------------------------------------------------------
__global__ __launch_bounds__(512)
void ctx_classifier_kernel(const __nv_bfloat16* __restrict__ CTX,
                           const float* __restrict__ WoWc,
                           const float* __restrict__ boWc,
                           const int*   __restrict__ num_turns,
                           float* __restrict__ out_all,
                           float* __restrict__ out_final)
{
    __shared__ float Wbot[C_DIM * WPAD];

    for (int i = threadIdx.x; i < D_DIM * C_DIM; i += 512) {
        const int dd = i / C_DIM, cc = i % C_DIM;
        Wbot[cc * WPAD + dd] = WoWc[i];
    }
    __syncthreads();

    const int warp = threadIdx.x >> 5;
    const int lane = threadIdx.x & 31;
    const int row0 = (blockIdx.x * 16 + warp) * 4;

    float acc[4][C_DIM];
    #pragma unroll
    for (int r = 0; r < 4; r++)
        #pragma unroll
        for (int c = 0; c < C_DIM; c++) acc[r][c] = 0.0f;

    #pragma unroll
    for (int i = 0; i < 3; i++) {
        const int off = (i * 32 + lane) * 8;
        float cf[4][8];
        #pragma unroll
        for (int r = 0; r < 4; r++) {
            uint4 u = *(const uint4*)&CTX[(size_t)(row0 + r) * D_DIM + off];
            const __nv_bfloat162* hh = reinterpret_cast<const __nv_bfloat162*>(&u);
            #pragma unroll
            for (int p = 0; p < 4; p++) {
                float2 cv = __bfloat1622float2(hh[p]);
                cf[r][2*p]   = cv.x;
                cf[r][2*p+1] = cv.y;
            }
        }
        #pragma unroll
        for (int c = 0; c < C_DIM; c++) {
            const float4 w0 = *(const float4*)&Wbot[c * WPAD + off];
            const float4 w1 = *(const float4*)&Wbot[c * WPAD + off + 4];
            #pragma unroll
            for (int r = 0; r < 4; r++)
                acc[r][c] += cf[r][0] * w0.x + cf[r][1] * w0.y
                           + cf[r][2] * w0.z + cf[r][3] * w0.w
                           + cf[r][4] * w1.x + cf[r][5] * w1.y
                           + cf[r][6] * w1.z + cf[r][7] * w1.w;
        }
    }

    #pragma unroll
    for (int r = 0; r < 4; r++)
        #pragma unroll
        for (int c = 0; c < C_DIM; c++) {
            acc[r][c] += __shfl_xor_sync(0xFFFFFFFFu, acc[r][c], 16);
            acc[r][c] += __shfl_xor_sync(0xFFFFFFFFu, acc[r][c], 8);
            acc[r][c] += __shfl_xor_sync(0xFFFFFFFFu, acc[r][c], 4);
            acc[r][c] += __shfl_xor_sync(0xFFFFFFFFu, acc[r][c], 2);
            acc[r][c] += __shfl_xor_sync(0xFFFFFFFFu, acc[r][c], 1);
        }

    if (lane == 0) {
        #pragma unroll
        for (int r = 0; r < 4; r++) {
            const int row = row0 + r;
            const int t = row & (T_DIM - 1);
            const int b = row >> 8;
            float* o = &out_all[(size_t)row * C_DIM];
            const bool fin = (t == num_turns[b] - 1);
            float* f = &out_final[(size_t)b * C_DIM];
            #pragma unroll
            for (int c = 0; c < C_DIM; c++) {
                const float v = o[c] + acc[r][c] + ((t > 0) ? boWc[c] : 0.0f);
                o[c] = v;
                if (fin) f[c] = v;
            }
        }
    }
}

// ---------------------------------------------------------------------------
// Launch
// ---------------------------------------------------------------------------
extern "C" void kernel_launch(void* const* d_in, const int* in_sizes, int n_in,
                              void* d_out, int out_size)
{
    const float* H  = (const float*)d_in[0];
    const float* Wq = (const float*)d_in[1];
    const float* bq = (const float*)d_in[2];
    const float* Wk = (const float*)d_in[3];
    const float* bk = (const float*)d_in[4];
    const float* Wv = (const float*)d_in[5];
    const float* bv = (const float*)d_in[6];
    const float* Wo = (const float*)d_in[7];
    const float* bo = (const float*)d_in[8];
    const float* Wc = (const float*)d_in[9];
    const float* bc = (const float*)d_in[10];
    const int*   nt = (const int*)  d_in[11];

    float* out_all   = (float*)d_out;
    float* out_final = (float*)d_out + (size_t)B_DIM * T_DIM * C_DIM;

    float *bp, *WoWcb, *boWcb;
    __nv_bfloat16 *Qb, *Kb, *Vb, *CTXb, *Abf, *Wbf;
    cudaGetSymbolAddress((void**)&Qb,    g_Q);
    cudaGetSymbolAddress((void**)&Kb,    g_K);
    cudaGetSymbolAddress((void**)&Vb,    g_V);
    cudaGetSymbolAddress((void**)&CTXb,  g_CTX);
    cudaGetSymbolAddress((void**)&Abf,   g_Abf);
    cudaGetSymbolAddress((void**)&Wbf,   g_Wbf);
    cudaGetSymbolAddress((void**)&bp,    g_bpack);
    cudaGetSymbolAddress((void**)&WoWcb, g_WoWc);
    cudaGetSymbolAddress((void**)&boWcb, g_boWc);

    // 1) fused prep
    prep_kernel<<<PREP_BLOCKS, 256>>>(H, Wq, Wk, Wv, bq, bk, bv, Wo, Wc, bo,
                                      Abf, Wbf, bp, WoWcb, boWcb);

    // 2) fused QKV projection + H-classifier tail blocks
    cudaFuncSetAttribute(bf16_gemm_kernel,
                         cudaFuncAttributeMaxDynamicSharedMemorySize, GEMM_SMEM_BYTES);
    bf16_gemm_kernel<<<GEMMH_BLOCKS, 256, GEMM_SMEM_BYTES>>>(
        Abf, Wbf, bp, Qb, Kb, Vb, H, Wc, bc, out_all);

    // 3) bf16 flash attention (Q in registers)
    cudaFuncSetAttribute(flash_attn_kernel,
                         cudaFuncAttributeMaxDynamicSharedMemorySize, ATT_SMEM_BYTES);
    flash_attn_kernel<<<B_DIM * NH_DIM, 512, ATT_SMEM_BYTES>>>(Qb, Kb, Vb, nt, CTXb);

    // 4) CTX classifier (RMW out_all) + final gather
    ctx_classifier_kernel<<<M_ROWS / 64, 512>>>(CTXb, WoWcb, boWcb,
                                                nt, out_all, out_final);
}

// round 16
// speedup vs baseline: 1.0168x; 1.0168x over previous
#include <cuda_runtime.h>
#include <cuda_bf16.h>
#include <math.h>
#include <stdint.h>

// Problem constants
#define B_DIM  64
#define T_DIM  256
#define D_DIM  768
#define NH_DIM 12
#define DH_DIM 64
#define C_DIM  7
#define M_ROWS (B_DIM * T_DIM)   // 16384
#define NQKV   (3 * D_DIM)       // 2304
#define KB16   (D_DIM / 16)      // 48
#define MB16   (M_ROWS / 16)     // 1024
#define NB8    (NQKV / 8)        // 288

// Prep-kernel block ranges
#define PA_BLOCKS  (MB16 * KB16 * 32 / 256)   // 6144
#define PW_BLOCKS  (NB8  * KB16 * 32 / 256)   // 1728
#define WC_BLOCKS  24
#define PREP_BLOCKS (PA_BLOCKS + PW_BLOCKS + WC_BLOCKS)

// ---------------------------------------------------------------------------
// Scratch (device globals; no runtime allocation allowed)
// ---------------------------------------------------------------------------
__device__ __nv_bfloat16 g_Q[(size_t)M_ROWS * D_DIM];
__device__ __nv_bfloat16 g_K[(size_t)M_ROWS * D_DIM];
__device__ __nv_bfloat16 g_V[(size_t)M_ROWS * D_DIM];
__device__ __nv_bfloat16 g_CTX[(size_t)M_ROWS * D_DIM];
__device__ __nv_bfloat16 g_Abf[(size_t)MB16 * KB16 * 256];
__device__ __nv_bfloat16 g_Wbf[(size_t)NB8  * KB16 * 128];
__device__ float g_bpack[NQKV];
__device__ float g_WoWc[D_DIM * C_DIM];
__device__ float g_boWc[C_DIM];

// ---------------------------------------------------------------------------
__device__ __forceinline__ uint32_t pack_bf2(float lo, float hi) {
    __nv_bfloat162 t = __floats2bfloat162_rn(lo, hi);
    return *reinterpret_cast<uint32_t*>(&t);
}

// ---------------------------------------------------------------------------
// Fused prep (proven): pack A fragments | pack W fragments + biases | WoWc.
// ---------------------------------------------------------------------------
__global__ __launch_bounds__(256)
void prep_kernel(const float* __restrict__ H,
                 const float* __restrict__ Wq, const float* __restrict__ Wk,
                 const float* __restrict__ Wv,
                 const float* __restrict__ bq, const float* __restrict__ bk,
                 const float* __restrict__ bv,
                 const float* __restrict__ Wo, const float* __restrict__ Wc,
                 const float* __restrict__ bo,
                 __nv_bfloat16* __restrict__ Abf,
                 __nv_bfloat16* __restrict__ Wbf,
                 float* __restrict__ bp,
                 float* __restrict__ WoWc, float* __restrict__ boWc)
{
    const int blk = blockIdx.x;

    if (blk < PA_BLOCKS) {
        const int idx  = blk * 256 + threadIdx.x;
        const int lane = idx & 31;
        const int kblk = (idx >> 5) % KB16;
        const int mblk = idx / (KB16 * 32);
        const int gid  = lane >> 2;
        const int tig  = lane & 3;
        const int m0 = mblk * 16 + gid;
        const int k0 = kblk * 16 + 2 * tig;

        float2 p00 = *(const float2*)&H[(size_t)m0 * D_DIM + k0];
        float2 p10 = *(const float2*)&H[(size_t)(m0 + 8) * D_DIM + k0];
        float2 p01 = *(const float2*)&H[(size_t)m0 * D_DIM + k0 + 8];
        float2 p11 = *(const float2*)&H[(size_t)(m0 + 8) * D_DIM + k0 + 8];

        uint4 out;
        out.x = pack_bf2(p00.x, p00.y);
        out.y = pack_bf2(p10.x, p10.y);
        out.z = pack_bf2(p01.x, p01.y);
        out.w = pack_bf2(p11.x, p11.y);
        *(uint4*)&Abf[(size_t)idx * 8] = out;

    } else if (blk < PA_BLOCKS + PW_BLOCKS) {
        const int idx  = (blk - PA_BLOCKS) * 256 + threadIdx.x;
        const int lane = idx & 31;
        const int kblk = (idx >> 5) % KB16;
        const int nblk = idx / (KB16 * 32);
        const int gid  = lane >> 2;
        const int tig  = lane & 3;
        const int n  = nblk * 8 + gid;
        const int k0 = kblk * 16 + 2 * tig;

        const float* W = (n < D_DIM) ? Wq : ((n < 2 * D_DIM) ? Wk : Wv);
        const int j = (n >= 2 * D_DIM) ? (n - 2 * D_DIM)
                     : ((n >= D_DIM) ? (n - D_DIM) : n);

        const float w0 = W[(size_t)k0 * D_DIM + j];
        const float w1 = W[(size_t)(k0 + 1) * D_DIM + j];
        const float w2 = W[(size_t)(k0 + 8) * D_DIM + j];
        const float w3 = W[(size_t)(k0 + 9) * D_DIM + j];

        uint2 out;
        out.x = pack_bf2(w0, w1);
        out.y = pack_bf2(w2, w3);
        *(uint2*)&Wbf[(size_t)idx * 4] = out;

        if (idx < NQKV) {
            float bv_;
            if (idx < D_DIM)            bv_ = bq[idx];
            else if (idx < 2 * D_DIM)   bv_ = bk[idx - D_DIM];
            else                        bv_ = bv[idx - 2 * D_DIM];
            bp[idx] = bv_;
        }

    } else {
        const int wblk   = blk - PA_BLOCKS - PW_BLOCKS;
        const int gwarp  = (wblk * 256 + threadIdx.x) >> 5;
        const int nwarps = (WC_BLOCKS * 256) >> 5;
        const int lane   = threadIdx.x & 31;

        for (int d = gwarp; d < D_DIM; d += nwarps) {
            float acc[C_DIM];
            #pragma unroll
            for (int c = 0; c < C_DIM; c++) acc[c] = 0.0f;
            for (int n = lane; n < D_DIM; n += 32) {
                const float w = Wo[(size_t)d * D_DIM + n];
                const float* wcr = &Wc[(size_t)(D_DIM + n) * C_DIM];
                #pragma unroll
                for (int c = 0; c < C_DIM; c++) acc[c] += w * wcr[c];
            }
            #pragma unroll
            for (int c = 0; c < C_DIM; c++) {
                acc[c] += __shfl_xor_sync(0xFFFFFFFFu, acc[c], 16);
                acc[c] += __shfl_xor_sync(0xFFFFFFFFu, acc[c], 8);
                acc[c] += __shfl_xor_sync(0xFFFFFFFFu, acc[c], 4);
                acc[c] += __shfl_xor_sync(0xFFFFFFFFu, acc[c], 2);
                acc[c] += __shfl_xor_sync(0xFFFFFFFFu, acc[c], 1);
            }
            if (lane == 0) {
                #pragma unroll
                for (int c = 0; c < C_DIM; c++) WoWc[d * C_DIM + c] = acc[c];
            }
        }

        const int g = wblk * 256 + threadIdx.x;
        if (g < C_DIM) {
            float a = 0.0f;
            for (int n = 0; n < D_DIM; n++)
                a += bo[n] * Wc[(size_t)(D_DIM + n) * C_DIM + g];
            boWc[g] = a;
        }
    }
}

// ---------------------------------------------------------------------------
// BF16 tensor-core GEMM v3: CTA 128x128, 512 threads = 16 warps (4m x 4n),
// warp tile 32x32 (low regs -> 2 CTAs/SM -> 32 warps/SM), BK=64, 3-stage.
// ---------------------------------------------------------------------------
#define A_STAGE_H 8192
#define B_STAGE_H 8192
#define GEMM_SMEM_BYTES (3 * (A_STAGE_H + B_STAGE_H) * 2)  // 98304

__device__ __forceinline__ void cp_async16(uint32_t smem_addr, const void* gptr) {
    asm volatile("cp.async.cg.shared.global [%0], [%1], 16;\n"
                 :: "r"(smem_addr), "l"(gptr));
}

__device__ __forceinline__ void mma_bf16_r(float* d,
                                           uint32_t a0, uint32_t a1,
                                           uint32_t a2, uint32_t a3,
                                           uint32_t b0, uint32_t b1) {
    asm volatile(
        "mma.sync.aligned.m16n8k16.row.col.f32.bf16.bf16.f32 "
        "{%0,%1,%2,%3}, {%4,%5,%6,%7}, {%8,%9}, {%0,%1,%2,%3};\n"
        : "+f"(d[0]), "+f"(d[1]), "+f"(d[2]), "+f"(d[3])
        : "r"(a0), "r"(a1), "r"(a2), "r"(a3), "r"(b0), "r"(b1));
}

__global__ __launch_bounds__(512, 2)
void bf16_gemm_kernel(const __nv_bfloat16* __restrict__ Abf,
                      const __nv_bfloat16* __restrict__ Wbf,
                      const float* __restrict__ bias,
                      __nv_bfloat16* __restrict__ C0,
                      __nv_bfloat16* __restrict__ C1,
                      __nv_bfloat16* __restrict__ C2)
{
    extern __shared__ __nv_bfloat16 smem[];
    __nv_bfloat16* As = smem;
    __nv_bfloat16* Bs = smem + 3 * A_STAGE_H;

    const int tid  = threadIdx.x;
    const int lane = tid & 31;
    const int warp = tid >> 5;           // 0..15
    const int gid  = lane >> 2;
    const int tig  = lane & 3;

    const int mrow0 = blockIdx.y * 8;
    const int nb0   = blockIdx.x * 16;
    const int block_row = blockIdx.y * 128;
    const int block_col = blockIdx.x * 128;

    const int seg = block_col / D_DIM;
    __nv_bfloat16* Cout = (seg == 0) ? C0 : (seg == 1 ? C1 : C2);
    const int out_col_base = block_col - seg * D_DIM;

    const uint32_t As_u32 = (uint32_t)__cvta_generic_to_shared(As);
    const uint32_t Bs_u32 = As_u32 + 3 * A_STAGE_H * 2;

    // warp layout: 4m x 4n; each warp 32 rows x 32 cols
    const int warp_mb = (warp & 3) * 2;      // 2 mb16 blocks
    const int warp_nb = (warp >> 2) * 4;     // 4 nb8 blocks

    float d[2][4][4];
    #pragma unroll
    for (int mi = 0; mi < 2; mi++)
        #pragma unroll
        for (int ni = 0; ni < 4; ni++)
            #pragma unroll
            for (int e = 0; e < 4; e++)
                d[mi][ni][e] = 0.0f;

    const int NITER = KB16 / 4;   // 12

    // stage copy: A 1024 chunks, B 1024 chunks; 2 each per thread (512 thr)
    auto do_stage = [&](int kb0, int s) {
        #pragma unroll
        for (int si = 0; si < 2; si++) {
            const int c   = tid + si * 512;
            const int mb  = c >> 7;
            const int kbl = (c >> 5) & 3;
            const int ch  = c & 31;
            cp_async16(As_u32 + (s * A_STAGE_H + c * 8) * 2,
                       Abf + (((size_t)(mrow0 + mb) * KB16 + kb0 + kbl) << 8) + ch * 8);
        }
        #pragma unroll
        for (int si = 0; si < 2; si++) {
            const int c   = tid + si * 512;
            const int nb  = c >> 6;
            const int kbl = (c >> 4) & 3;
            const int ch  = c & 15;
            cp_async16(Bs_u32 + (s * B_STAGE_H + c * 8) * 2,
                       Wbf + (((size_t)(nb0 + nb) * KB16 + kb0 + kbl) << 7) + ch * 8);
        }
        asm volatile("cp.async.commit_group;\n");
    };

    do_stage(0, 0);
    do_stage(4, 1);

    for (int it = 0; it < NITER; it++) {
        if (it + 1 < NITER) asm volatile("cp.async.wait_group 1;\n");
        else                asm volatile("cp.async.wait_group 0;\n");
        __syncthreads();

        if (it + 2 < NITER) do_stage((it + 2) * 4, (it + 2) % 3);

        const int s = it % 3;
        const uint4* As4 = (const uint4*)As + s * (A_STAGE_H / 8);
        const uint2* Bs2 = (const uint2*)Bs + s * (B_STAGE_H / 4);

        #pragma unroll
        for (int kb = 0; kb < 4; kb++) {
            uint4 afr[2];
            #pragma unroll
            for (int mi = 0; mi < 2; mi++)
                afr[mi] = As4[((warp_mb + mi) * 4 + kb) * 32 + lane];
            uint2 bfr[4];
            #pragma unroll
            for (int ni = 0; ni < 4; ni++)
                bfr[ni] = Bs2[((warp_nb + ni) * 4 + kb) * 32 + lane];
            #pragma unroll
            for (int mi = 0; mi < 2; mi++)
                #pragma unroll
                for (int ni = 0; ni < 4; ni++)
                    mma_bf16_r(d[mi][ni], afr[mi].x, afr[mi].y, afr[mi].z,
                               afr[mi].w, bfr[ni].x, bfr[ni].y);
        }
    }

    #pragma unroll
    for (int mi = 0; mi < 2; mi++) {
        const int r0 = block_row + (warp & 3) * 32 + mi * 16 + gid;
        const int r1 = r0 + 8;
        #pragma unroll
        for (int ni = 0; ni < 4; ni++) {
            const int cg = block_col + (warp >> 2) * 32 + ni * 8 + 2 * tig;
            const int cl = out_col_base + (warp >> 2) * 32 + ni * 8 + 2 * tig;
            const float b0 = bias[cg], b1 = bias[cg + 1];
            *(uint32_t*)&Cout[(size_t)r0 * D_DIM + cl] =
                pack_bf2(d[mi][ni][0] + b0, d[mi][ni][1] + b1);
            *(uint32_t*)&Cout[(size_t)r1 * D_DIM + cl] =
                pack_bf2(d[mi][ni][2] + b0, d[mi][ni][3] + b1);
        }
    }
}

// ---------------------------------------------------------------------------
// BF16 flash-attention v3 (proven): Q fragments in registers.
// ---------------------------------------------------------------------------
#define AQ_ST 72
#define AV_ST 264
#define ATT_SMEM_BYTES ((T_DIM * AQ_ST + DH_DIM * AV_ST) * 2)  // 70656

__global__ __launch_bounds__(512)
void flash_attn_kernel(const __nv_bfloat16* __restrict__ Q,
                       const __nv_bfloat16* __restrict__ K,
                       const __nv_bfloat16* __restrict__ V,
                       const int*   __restrict__ num_turns,
                       __nv_bfloat16* __restrict__ CTX)
{
    const int b = blockIdx.x / NH_DIM;
    const int h = blockIdx.x % NH_DIM;

    extern __shared__ __nv_bfloat16 asm_[];
    __nv_bfloat16* Ks = asm_;
    __nv_bfloat16* Vt = Ks + T_DIM * AQ_ST;

    const size_t base = ((size_t)b * T_DIM * NH_DIM + h) * DH_DIM;
    const int tid = threadIdx.x;

    for (int idx = tid; idx < T_DIM * 8; idx += 512) {
        const int t  = idx >> 3;
        const int c8 = (idx & 7) * 8;
        *(uint4*)&Ks[t * AQ_ST + c8] =
            *(const uint4*)&K[base + (size_t)t * D_DIM + c8];
    }
    for (int idx = tid; idx < (T_DIM / 2) * 8; idx += 512) {
        const int tp = idx >> 3;
        const int c8 = (idx & 7) * 8;
        const int t0 = tp * 2;
        const uint4 v0 = *(const uint4*)&V[base + (size_t)t0 * D_DIM + c8];
        const uint4 v1 = *(const uint4*)&V[base + (size_t)(t0 + 1) * D_DIM + c8];
        const uint16_t* h0 = reinterpret_cast<const uint16_t*>(&v0);
        const uint16_t* h1 = reinterpret_cast<const uint16_t*>(&v1);
        #pragma unroll
        for (int j = 0; j < 8; j++) {
            const uint32_t pr = (uint32_t)h0[j] | ((uint32_t)h1[j] << 16);
            *(uint32_t*)&Vt[(c8 + j) * AV_ST + t0] = pr;
        }
    }

    const int warp = tid >> 5;
    const int lane = tid & 31;
    const int gid  = lane >> 2;
    const int tig  = lane & 3;

    const int q0 = warp * 16 + gid;
    const int q1 = q0 + 8;
    const int ntv  = num_turns[b];
    const int lim0 = min(q0, ntv);
    const int lim1 = min(q1, ntv);

    uint32_t qfr[4][4];
    {
        const __nv_bfloat16* qr0 = &Q[base + (size_t)q0 * D_DIM];
        const __nv_bfloat16* qr1 = &Q[base + (size_t)q1 * D_DIM];
        #pragma unroll
        for (int kt = 0; kt < 4; kt++) {
            const int dh = kt * 16;
            qfr[kt][0] = *(const uint32_t*)&qr0[dh + 2 * tig];
            qfr[kt][1] = *(const uint32_t*)&qr1[dh + 2 * tig];
            qfr[kt][2] = *(const uint32_t*)&qr0[dh + 8 + 2 * tig];
            qfr[kt][3] = *(const uint32_t*)&qr1[dh + 8 + 2 * tig];
        }
    }
    __syncthreads();

    const int lim_max = min(warp * 16 + 15, ntv);
    const int nch = (lim_max + 63) >> 6;

    float octx[8][4];
    #pragma unroll
    for (int i = 0; i < 8; i++)
        #pragma unroll
        for (int j = 0; j < 4; j++) octx[i][j] = 0.0f;
    float m0 = -1e30f, m1 = -1e30f, l0 = 0.0f, l1 = 0.0f;

    for (int ch = 0; ch < nch; ch++) {
        const int kbase = ch * 64;

        float s[8][4];
        #pragma unroll
        for (int i = 0; i < 8; i++)
            #pragma unroll
            for (int j = 0; j < 4; j++) s[i][j] = 0.0f;

        #pragma unroll
        for (int kt = 0; kt < 4; kt++) {
            const int dh = kt * 16;
            #pragma unroll
            for (int nt8 = 0; nt8 < 8; nt8++) {
                const int krow = kbase + nt8 * 8 + gid;
                const uint32_t b0 = *(const uint32_t*)&Ks[krow * AQ_ST + dh + 2 * tig];
                const uint32_t b1 = *(const uint32_t*)&Ks[krow * AQ_ST + dh + 8 + 2 * tig];
                mma_bf16_r(s[nt8], qfr[kt][0], qfr[kt][1], qfr[kt][2],
                           qfr[kt][3], b0, b1);
            }
        }

        float mx0 = -1e30f, mx1 = -1e30f;
        #pragma unroll
        for (int i = 0; i < 8; i++) {
            const int kc = kbase + i * 8 + 2 * tig;
            s[i][0] = (kc     < lim0) ? s[i][0] * 0.125f : -1e30f;
            s[i][1] = (kc + 1 < lim0) ? s[i][1] * 0.125f : -1e30f;
            s[i][2] = (kc     < lim1) ? s[i][2] * 0.125f : -1e30f;
            s[i][3] = (kc + 1 < lim1) ? s[i][3] * 0.125f : -1e30f;
            mx0 = fmaxf(mx0, fmaxf(s[i][0], s[i][1]));
            mx1 = fmaxf(mx1, fmaxf(s[i][2], s[i][3]));
        }
        mx0 = fmaxf(mx0, __shfl_xor_sync(0xFFFFFFFFu, mx0, 1));
        mx0 = fmaxf(mx0, __shfl_xor_sync(0xFFFFFFFFu, mx0, 2));
        mx1 = fmaxf(mx1, __shfl_xor_sync(0xFFFFFFFFu, mx1, 1));
        mx1 = fmaxf(mx1, __shfl_xor_sync(0xFFFFFFFFu, mx1, 2));

        const float nm0 = fmaxf(m0, mx0);
        const float nm1 = fmaxf(m1, mx1);
        const float corr0 = __expf(m0 - nm0);
        const float corr1 = __expf(m1 - nm1);
        m0 = nm0; m1 = nm1;
        l0 *= corr0; l1 *= corr1;
        #pragma unroll
        for (int i = 0; i < 8; i++) {
            octx[i][0] *= corr0; octx[i][1] *= corr0;
            octx[i][2] *= corr1; octx[i][3] *= corr1;
        }

        #pragma unroll
        for (int i = 0; i < 8; i++) {
            const float p0 = __expf(s[i][0] - m0);
            const float p1 = __expf(s[i][1] - m0);
            const float p2 = __expf(s[i][2] - m1);
            const float p3 = __expf(s[i][3] - m1);
            l0 += p0 + p1;  l1 += p2 + p3;
            s[i][0] = p0; s[i][1] = p1; s[i][2] = p2; s[i][3] = p3;
        }

        #pragma unroll
        for (int kt16 = 0; kt16 < 4; kt16++) {
            const int i0 = 2 * kt16, i1 = i0 + 1;
            const uint32_t a0 = pack_bf2(s[i0][0], s[i0][1]);
            const uint32_t a1 = pack_bf2(s[i0][2], s[i0][3]);
            const uint32_t a2 = pack_bf2(s[i1][0], s[i1][1]);
            const uint32_t a3 = pack_bf2(s[i1][2], s[i1][3]);
            const int kb = kbase + kt16 * 16;
            #pragma unroll
            for (int ndh = 0; ndh < 8; ndh++) {
                const int vrow = ndh * 8 + gid;
                const uint32_t b0 = *(const uint32_t*)&Vt[vrow * AV_ST + kb + 2 * tig];
                const uint32_t b1 = *(const uint32_t*)&Vt[vrow * AV_ST + kb + 8 + 2 * tig];
                mma_bf16_r(octx[ndh], a0, a1, a2, a3, b0, b1);
            }
        }
    }

    l0 += __shfl_xor_sync(0xFFFFFFFFu, l0, 1);
    l0 += __shfl_xor_sync(0xFFFFFFFFu, l0, 2);
    l1 += __shfl_xor_sync(0xFFFFFFFFu, l1, 1);
    l1 += __shfl_xor_sync(0xFFFFFFFFu, l1, 2);
    const float inv0 = (lim0 > 0) ? 1.0f / l0 : 0.0f;
    const float inv1 = (lim1 > 0) ? 1.0f / l1 : 0.0f;

    __nv_bfloat16* o0 = &CTX[base + (size_t)q0 * D_DIM];
    __nv_bfloat16* o1 = &CTX[base + (size_t)q1 * D_DIM];
    #pragma unroll
    for (int ndh = 0; ndh < 8; ndh++) {
        const int c = ndh * 8 + 2 * tig;
        *(uint32_t*)&o0[c] = pack_bf2(octx[ndh][0] * inv0, octx[ndh][1] * inv0);
        *(uint32_t*)&o1[c] = pack_bf2(octx[ndh][2] * inv1, octx[ndh][3] * inv1);
    }
}

// ---------------------------------------------------------------------------
// Classifier (round 10 proven): warp per 4 rows, H + CTX fused, transposed
// conflict-free smem weights, final gather.
// ---------------------------------------------------------------------------
#define WPAD 772

__global__ __launch_bounds__(512)
void classifier_kernel(const float* __restrict__ H,
                       const __nv_bfloat16* __restrict__ CTX,
                       const float* __restrict__ Wc,
                       const float* __restrict__ bc,
                       const float* __restrict__ WoWc,
                       const float* __restrict__ boWc,
                       const int*   __restrict__ num_turns,
                       float* __restrict__ out_all,
                       float* __restrict__ out_final)
{
    __shared__ float Wtop[C_DIM * WPAD];
    __shared__ float Wbot[C_DIM * WPAD];

    for (int i = threadIdx.x; i < D_DIM * C_DIM; i += 512) {
        const int dd = i / C_DIM, cc = i % C_DIM;
        Wtop[cc * WPAD + dd] = Wc[i];
        Wbot[cc * WPAD + dd] = WoWc[i];
    }
    __syncthreads();

    const int warp = threadIdx.x >> 5;
    const int lane = threadIdx.x & 31;
    const int row0 = (blockIdx.x * 16 + warp) * 4;

    float acc[4][C_DIM];
    #pragma unroll
    for (int r = 0; r < 4; r++)
        #pragma unroll
        for (int c = 0; c < C_DIM; c++) acc[r][c] = 0.0f;

    #pragma unroll
    for (int i = 0; i < 6; i++) {
        const int off = (i * 32 + lane) * 4;
        float4 h4[4];
        #pragma unroll
        for (int r = 0; r < 4; r++)
            h4[r] = *(const float4*)&H[(size_t)(row0 + r) * D_DIM + off];
        #pragma unroll
        for (int c = 0; c < C_DIM; c++) {
            const float4 w = *(const float4*)&Wtop[c * WPAD + off];
            #pragma unroll
            for (int r = 0; r < 4; r++)
                acc[r][c] += h4[r].x * w.x + h4[r].y * w.y
                           + h4[r].z * w.z + h4[r].w * w.w;
        }
    }

    #pragma unroll
    for (int i = 0; i < 3; i++) {
        const int off = (i * 32 + lane) * 8;
        float cf[4][8];
        #pragma unroll
        for (int r = 0; r < 4; r++) {
            uint4 u = *(const uint4*)&CTX[(size_t)(row0 + r) * D_DIM + off];
            const __nv_bfloat162* hh = reinterpret_cast<const __nv_bfloat162*>(&u);
            #pragma unroll
            for (int p = 0; p < 4; p++) {
                float2 cv = __bfloat1622float2(hh[p]);
                cf[r][2*p]   = cv.x;
                cf[r][2*p+1] = cv.y;
            }
        }
        #pragma unroll
        for (int c = 0; c < C_DIM; c++) {
            const float4 w0 = *(const float4*)&Wbot[c * WPAD + off];
            const float4 w1 = *(const float4*)&Wbot[c * WPAD + off + 4];
            #pragma unroll
            for (int r = 0; r < 4; r++)
                acc[r][c] += cf[r][0] * w0.x + cf[r][1] * w0.y
                           + cf[r][2] * w0.z + cf[r][3] * w0.w
                           + cf[r][4] * w1.x + cf[r][5] * w1.y
                           + cf[r][6] * w1.z + cf[r][7] * w1.w;
        }
    }

    #pragma unroll
    for (int r = 0; r < 4; r++)
        #pragma unroll
        for (int c = 0; c < C_DIM; c++) {
            acc[r][c] += __shfl_xor_sync(0xFFFFFFFFu, acc[r][c], 16);
            acc[r][c] += __shfl_xor_sync(0xFFFFFFFFu, acc[r][c], 8);
            acc[r][c] += __shfl_xor_sync(0xFFFFFFFFu, acc[r][c], 4);
            acc[r][c] += __shfl_xor_sync(0xFFFFFFFFu, acc[r][c], 2);
            acc[r][c] += __shfl_xor_sync(0xFFFFFFFFu, acc[r][c], 1);
        }

    if (lane == 0) {
        #pragma unroll
        for (int r = 0; r < 4; r++) {
            const int row = row0 + r;
            const int t = row & (T_DIM - 1);
            const int b = row >> 8;
            float* o = &out_all[(size_t)row * C_DIM];
            const bool fin = (t == num_turns[b] - 1);
            float* f = &out_final[(size_t)b * C_DIM];
            #pragma unroll
            for (int c = 0; c < C_DIM; c++) {
                const float v = acc[r][c] + bc[c] + ((t > 0) ? boWc[c] : 0.0f);
                o[c] = v;
                if (fin) f[c] = v;
            }
        }
    }
}

// ---------------------------------------------------------------------------
// Launch
// ---------------------------------------------------------------------------
extern "C" void kernel_launch(void* const* d_in, const int* in_sizes, int n_in,
                              void* d_out, int out_size)
{
    const float* H  = (const float*)d_in[0];
    const float* Wq = (const float*)d_in[1];
    const float* bq = (const float*)d_in[2];
    const float* Wk = (const float*)d_in[3];
    const float* bk = (const float*)d_in[4];
    const float* Wv = (const float*)d_in[5];
    const float* bv = (const float*)d_in[6];
    const float* Wo = (const float*)d_in[7];
    const float* bo = (const float*)d_in[8];
    const float* Wc = (const float*)d_in[9];
    const float* bc = (const float*)d_in[10];
    const int*   nt = (const int*)  d_in[11];

    float* out_all   = (float*)d_out;
    float* out_final = (float*)d_out + (size_t)B_DIM * T_DIM * C_DIM;

    float *bp, *WoWcb, *boWcb;
    __nv_bfloat16 *Qb, *Kb, *Vb, *CTXb, *Abf, *Wbf;
    cudaGetSymbolAddress((void**)&Qb,    g_Q);
    cudaGetSymbolAddress((void**)&Kb,    g_K);
    cudaGetSymbolAddress((void**)&Vb,    g_V);
    cudaGetSymbolAddress((void**)&CTXb,  g_CTX);
    cudaGetSymbolAddress((void**)&Abf,   g_Abf);
    cudaGetSymbolAddress((void**)&Wbf,   g_Wbf);
    cudaGetSymbolAddress((void**)&bp,    g_bpack);
    cudaGetSymbolAddress((void**)&WoWcb, g_WoWc);
    cudaGetSymbolAddress((void**)&boWcb, g_boWc);

    // 1) fused prep
    prep_kernel<<<PREP_BLOCKS, 256>>>(H, Wq, Wk, Wv, bq, bk, bv, Wo, Wc, bo,
                                      Abf, Wbf, bp, WoWcb, boWcb);

    // 2) fused QKV projection (16 warps/CTA, 32 warps/SM)
    cudaFuncSetAttribute(bf16_gemm_kernel,
                         cudaFuncAttributeMaxDynamicSharedMemorySize, GEMM_SMEM_BYTES);
    {
        dim3 grid(NQKV / 128, M_ROWS / 128);   // (18, 128)
        bf16_gemm_kernel<<<grid, 512, GEMM_SMEM_BYTES>>>(Abf, Wbf, bp, Qb, Kb, Vb);
    }

    // 3) bf16 flash attention (Q in registers)
    cudaFuncSetAttribute(flash_attn_kernel,
                         cudaFuncAttributeMaxDynamicSharedMemorySize, ATT_SMEM_BYTES);
    flash_attn_kernel<<<B_DIM * NH_DIM, 512, ATT_SMEM_BYTES>>>(Qb, Kb, Vb, nt, CTXb);

    // 4) classifier (fused H+CTX, 4 rows/warp) + final gather
    classifier_kernel<<<M_ROWS / 64, 512>>>(H, CTXb, Wc, bc, WoWcb, boWcb,
                                            nt, out_all, out_final);
}

// round 17
// speedup vs baseline: 1.0339x; 1.0168x over previous
#include <cuda_runtime.h>
#include <cuda_bf16.h>
#include <math.h>
#include <stdint.h>

// Problem constants
#define B_DIM  64
#define T_DIM  256
#define D_DIM  768
#define NH_DIM 12
#define DH_DIM 64
#define C_DIM  7
#define M_ROWS (B_DIM * T_DIM)   // 16384
#define NQKV   (3 * D_DIM)       // 2304
#define KB16   (D_DIM / 16)      // 48
#define MB16   (M_ROWS / 16)     // 1024
#define NB8    (NQKV / 8)        // 288

// Prep-kernel block ranges
#define PA_BLOCKS  (MB16 * KB16 * 32 / 256)   // 6144
#define PW_BLOCKS  (NB8  * KB16 * 32 / 256)   // 1728
#define WC_BLOCKS  24
#define PREP_BLOCKS (PA_BLOCKS + PW_BLOCKS + WC_BLOCKS)

// ---------------------------------------------------------------------------
// Scratch (device globals; no runtime allocation allowed)
// ---------------------------------------------------------------------------
__device__ __nv_bfloat16 g_Q[(size_t)M_ROWS * D_DIM];
__device__ __nv_bfloat16 g_K[(size_t)M_ROWS * D_DIM];
__device__ __nv_bfloat16 g_V[(size_t)M_ROWS * D_DIM];
__device__ __nv_bfloat16 g_CTX[(size_t)M_ROWS * D_DIM];
__device__ __nv_bfloat16 g_Abf[(size_t)MB16 * KB16 * 256];
__device__ __nv_bfloat16 g_Wbf[(size_t)NB8  * KB16 * 128];
__device__ float g_bpack[NQKV];
__device__ float g_WoWc[D_DIM * C_DIM];
__device__ float g_boWc[C_DIM];

// ---------------------------------------------------------------------------
__device__ __forceinline__ uint32_t pack_bf2(float lo, float hi) {
    __nv_bfloat162 t = __floats2bfloat162_rn(lo, hi);
    return *reinterpret_cast<uint32_t*>(&t);
}

// ---------------------------------------------------------------------------
// Fused prep (proven): pack A fragments | pack W fragments + biases | WoWc.
// ---------------------------------------------------------------------------
__global__ __launch_bounds__(256)
void prep_kernel(const float* __restrict__ H,
                 const float* __restrict__ Wq, const float* __restrict__ Wk,
                 const float* __restrict__ Wv,
                 const float* __restrict__ bq, const float* __restrict__ bk,
                 const float* __restrict__ bv,
                 const float* __restrict__ Wo, const float* __restrict__ Wc,
                 const float* __restrict__ bo,
                 __nv_bfloat16* __restrict__ Abf,
                 __nv_bfloat16* __restrict__ Wbf,
                 float* __restrict__ bp,
                 float* __restrict__ WoWc, float* __restrict__ boWc)
{
    const int blk = blockIdx.x;

    if (blk < PA_BLOCKS) {
        const int idx  = blk * 256 + threadIdx.x;
        const int lane = idx & 31;
        const int kblk = (idx >> 5) % KB16;
        const int mblk = idx / (KB16 * 32);
        const int gid  = lane >> 2;
        const int tig  = lane & 3;
        const int m0 = mblk * 16 + gid;
        const int k0 = kblk * 16 + 2 * tig;

        float2 p00 = *(const float2*)&H[(size_t)m0 * D_DIM + k0];
        float2 p10 = *(const float2*)&H[(size_t)(m0 + 8) * D_DIM + k0];
        float2 p01 = *(const float2*)&H[(size_t)m0 * D_DIM + k0 + 8];
        float2 p11 = *(const float2*)&H[(size_t)(m0 + 8) * D_DIM + k0 + 8];

        uint4 out;
        out.x = pack_bf2(p00.x, p00.y);
        out.y = pack_bf2(p10.x, p10.y);
        out.z = pack_bf2(p01.x, p01.y);
        out.w = pack_bf2(p11.x, p11.y);
        *(uint4*)&Abf[(size_t)idx * 8] = out;

    } else if (blk < PA_BLOCKS + PW_BLOCKS) {
        const int idx  = (blk - PA_BLOCKS) * 256 + threadIdx.x;
        const int lane = idx & 31;
        const int kblk = (idx >> 5) % KB16;
        const int nblk = idx / (KB16 * 32);
        const int gid  = lane >> 2;
        const int tig  = lane & 3;
        const int n  = nblk * 8 + gid;
        const int k0 = kblk * 16 + 2 * tig;

        const float* W = (n < D_DIM) ? Wq : ((n < 2 * D_DIM) ? Wk : Wv);
        const int j = (n >= 2 * D_DIM) ? (n - 2 * D_DIM)
                     : ((n >= D_DIM) ? (n - D_DIM) : n);

        const float w0 = W[(size_t)k0 * D_DIM + j];
        const float w1 = W[(size_t)(k0 + 1) * D_DIM + j];
        const float w2 = W[(size_t)(k0 + 8) * D_DIM + j];
        const float w3 = W[(size_t)(k0 + 9) * D_DIM + j];

        uint2 out;
        out.x = pack_bf2(w0, w1);
        out.y = pack_bf2(w2, w3);
        *(uint2*)&Wbf[(size_t)idx * 4] = out;

        if (idx < NQKV) {
            float bv_;
            if (idx < D_DIM)            bv_ = bq[idx];
            else if (idx < 2 * D_DIM)   bv_ = bk[idx - D_DIM];
            else                        bv_ = bv[idx - 2 * D_DIM];
            bp[idx] = bv_;
        }

    } else {
        const int wblk   = blk - PA_BLOCKS - PW_BLOCKS;
        const int gwarp  = (wblk * 256 + threadIdx.x) >> 5;
        const int nwarps = (WC_BLOCKS * 256) >> 5;
        const int lane   = threadIdx.x & 31;

        for (int d = gwarp; d < D_DIM; d += nwarps) {
            float acc[C_DIM];
            #pragma unroll
            for (int c = 0; c < C_DIM; c++) acc[c] = 0.0f;
            for (int n = lane; n < D_DIM; n += 32) {
                const float w = Wo[(size_t)d * D_DIM + n];
                const float* wcr = &Wc[(size_t)(D_DIM + n) * C_DIM];
                #pragma unroll
                for (int c = 0; c < C_DIM; c++) acc[c] += w * wcr[c];
            }
            #pragma unroll
            for (int c = 0; c < C_DIM; c++) {
                acc[c] += __shfl_xor_sync(0xFFFFFFFFu, acc[c], 16);
                acc[c] += __shfl_xor_sync(0xFFFFFFFFu, acc[c], 8);
                acc[c] += __shfl_xor_sync(0xFFFFFFFFu, acc[c], 4);
                acc[c] += __shfl_xor_sync(0xFFFFFFFFu, acc[c], 2);
                acc[c] += __shfl_xor_sync(0xFFFFFFFFu, acc[c], 1);
            }
            if (lane == 0) {
                #pragma unroll
                for (int c = 0; c < C_DIM; c++) WoWc[d * C_DIM + c] = acc[c];
            }
        }

        const int g = wblk * 256 + threadIdx.x;
        if (g < C_DIM) {
            float a = 0.0f;
            for (int n = 0; n < D_DIM; n++)
                a += bo[n] * Wc[(size_t)(D_DIM + n) * C_DIM + g];
            boWc[g] = a;
        }
    }
}

// ---------------------------------------------------------------------------
// BF16 tensor-core GEMM (round 10, proven fastest): 256 thr, 8 warps,
// warp tile 32x64, BK=64, 3-stage cp.async.
// ---------------------------------------------------------------------------
#define A_STAGE_H 8192
#define B_STAGE_H 8192
#define GEMM_SMEM_BYTES (3 * (A_STAGE_H + B_STAGE_H) * 2)  // 98304

__device__ __forceinline__ void cp_async16(uint32_t smem_addr, const void* gptr) {
    asm volatile("cp.async.cg.shared.global [%0], [%1], 16;\n"
                 :: "r"(smem_addr), "l"(gptr));
}

__device__ __forceinline__ void mma_bf16_r(float* d,
                                           uint32_t a0, uint32_t a1,
                                           uint32_t a2, uint32_t a3,
                                           uint32_t b0, uint32_t b1) {
    asm volatile(
        "mma.sync.aligned.m16n8k16.row.col.f32.bf16.bf16.f32 "
        "{%0,%1,%2,%3}, {%4,%5,%6,%7}, {%8,%9}, {%0,%1,%2,%3};\n"
        : "+f"(d[0]), "+f"(d[1]), "+f"(d[2]), "+f"(d[3])
        : "r"(a0), "r"(a1), "r"(a2), "r"(a3), "r"(b0), "r"(b1));
}

__global__ __launch_bounds__(256)
void bf16_gemm_kernel(const __nv_bfloat16* __restrict__ Abf,
                      const __nv_bfloat16* __restrict__ Wbf,
                      const float* __restrict__ bias,
                      __nv_bfloat16* __restrict__ C0,
                      __nv_bfloat16* __restrict__ C1,
                      __nv_bfloat16* __restrict__ C2)
{
    extern __shared__ __nv_bfloat16 smem[];
    __nv_bfloat16* As = smem;
    __nv_bfloat16* Bs = smem + 3 * A_STAGE_H;

    const int tid  = threadIdx.x;
    const int lane = tid & 31;
    const int warp = tid >> 5;
    const int gid  = lane >> 2;
    const int tig  = lane & 3;

    const int mrow0 = blockIdx.y * 8;
    const int nb0   = blockIdx.x * 16;
    const int block_row = blockIdx.y * 128;
    const int block_col = blockIdx.x * 128;

    const int seg = block_col / D_DIM;
    __nv_bfloat16* Cout = (seg == 0) ? C0 : (seg == 1 ? C1 : C2);
    const int out_col_base = block_col - seg * D_DIM;

    const uint32_t As_u32 = (uint32_t)__cvta_generic_to_shared(As);
    const uint32_t Bs_u32 = As_u32 + 3 * A_STAGE_H * 2;

    float d[2][8][4];
    #pragma unroll
    for (int mi = 0; mi < 2; mi++)
        #pragma unroll
        for (int ni = 0; ni < 8; ni++)
            #pragma unroll
            for (int e = 0; e < 4; e++)
                d[mi][ni][e] = 0.0f;

    const int NITER = KB16 / 4;   // 12

    auto do_stage = [&](int kb0, int s) {
        #pragma unroll
        for (int si = 0; si < 4; si++) {
            const int c   = tid + si * 256;
            const int mb  = c >> 7;
            const int kbl = (c >> 5) & 3;
            const int ch  = c & 31;
            cp_async16(As_u32 + (s * A_STAGE_H + c * 8) * 2,
                       Abf + (((size_t)(mrow0 + mb) * KB16 + kb0 + kbl) << 8) + ch * 8);
        }
        #pragma unroll
        for (int si = 0; si < 4; si++) {
            const int c   = tid + si * 256;
            const int nb  = c >> 6;
            const int kbl = (c >> 4) & 3;
            const int ch  = c & 15;
            cp_async16(Bs_u32 + (s * B_STAGE_H + c * 8) * 2,
                       Wbf + (((size_t)(nb0 + nb) * KB16 + kb0 + kbl) << 7) + ch * 8);
        }
        asm volatile("cp.async.commit_group;\n");
    };

    do_stage(0, 0);
    do_stage(4, 1);

    const int warp_mb = (warp & 3) * 2;
    const int warp_nb = (warp >> 2) * 8;

    for (int it = 0; it < NITER; it++) {
        if (it + 1 < NITER) asm volatile("cp.async.wait_group 1;\n");
        else                asm volatile("cp.async.wait_group 0;\n");
        __syncthreads();

        if (it + 2 < NITER) do_stage((it + 2) * 4, (it + 2) % 3);

        const int s = it % 3;
        const uint4* As4 = (const uint4*)As + s * (A_STAGE_H / 8);
        const uint2* Bs2 = (const uint2*)Bs + s * (B_STAGE_H / 4);

        #pragma unroll
        for (int kb = 0; kb < 4; kb++) {
            uint4 afr[2];
            #pragma unroll
            for (int mi = 0; mi < 2; mi++)
                afr[mi] = As4[((warp_mb + mi) * 4 + kb) * 32 + lane];
            uint2 bfr[8];
            #pragma unroll
            for (int ni = 0; ni < 8; ni++)
                bfr[ni] = Bs2[((warp_nb + ni) * 4 + kb) * 32 + lane];
            #pragma unroll
            for (int mi = 0; mi < 2; mi++)
                #pragma unroll
                for (int ni = 0; ni < 8; ni++)
                    mma_bf16_r(d[mi][ni], afr[mi].x, afr[mi].y, afr[mi].z,
                               afr[mi].w, bfr[ni].x, bfr[ni].y);
        }
    }

    #pragma unroll
    for (int mi = 0; mi < 2; mi++) {
        const int r0 = block_row + (warp & 3) * 32 + mi * 16 + gid;
        const int r1 = r0 + 8;
        #pragma unroll
        for (int ni = 0; ni < 8; ni++) {
            const int cg = block_col + (warp >> 2) * 64 + ni * 8 + 2 * tig;
            const int cl = out_col_base + (warp >> 2) * 64 + ni * 8 + 2 * tig;
            const float b0 = bias[cg], b1 = bias[cg + 1];
            *(uint32_t*)&Cout[(size_t)r0 * D_DIM + cl] =
                pack_bf2(d[mi][ni][0] + b0, d[mi][ni][1] + b1);
            *(uint32_t*)&Cout[(size_t)r1 * D_DIM + cl] =
                pack_bf2(d[mi][ni][2] + b0, d[mi][ni][3] + b1);
        }
    }
}

// ---------------------------------------------------------------------------
// BF16 flash-attention v3 (round 14, proven): Q fragments in registers,
// K/Vt in smem, shuffle-free P packing.
// ---------------------------------------------------------------------------
#define AQ_ST 72
#define AV_ST 264
#define ATT_SMEM_BYTES ((T_DIM * AQ_ST + DH_DIM * AV_ST) * 2)  // 70656

__global__ __launch_bounds__(512)
void flash_attn_kernel(const __nv_bfloat16* __restrict__ Q,
                       const __nv_bfloat16* __restrict__ K,
                       const __nv_bfloat16* __restrict__ V,
                       const int*   __restrict__ num_turns,
                       __nv_bfloat16* __restrict__ CTX)
{
    const int b = blockIdx.x / NH_DIM;
    const int h = blockIdx.x % NH_DIM;

    extern __shared__ __nv_bfloat16 asm_[];
    __nv_bfloat16* Ks = asm_;
    __nv_bfloat16* Vt = Ks + T_DIM * AQ_ST;

    const size_t base = ((size_t)b * T_DIM * NH_DIM + h) * DH_DIM;
    const int tid = threadIdx.x;

    for (int idx = tid; idx < T_DIM * 8; idx += 512) {
        const int t  = idx >> 3;
        const int c8 = (idx & 7) * 8;
        *(uint4*)&Ks[t * AQ_ST + c8] =
            *(const uint4*)&K[base + (size_t)t * D_DIM + c8];
    }
    for (int idx = tid; idx < (T_DIM / 2) * 8; idx += 512) {
        const int tp = idx >> 3;
        const int c8 = (idx & 7) * 8;
        const int t0 = tp * 2;
        const uint4 v0 = *(const uint4*)&V[base + (size_t)t0 * D_DIM + c8];
        const uint4 v1 = *(const uint4*)&V[base + (size_t)(t0 + 1) * D_DIM + c8];
        const uint16_t* h0 = reinterpret_cast<const uint16_t*>(&v0);
        const uint16_t* h1 = reinterpret_cast<const uint16_t*>(&v1);
        #pragma unroll
        for (int j = 0; j < 8; j++) {
            const uint32_t pr = (uint32_t)h0[j] | ((uint32_t)h1[j] << 16);
            *(uint32_t*)&Vt[(c8 + j) * AV_ST + t0] = pr;
        }
    }

    const int warp = tid >> 5;
    const int lane = tid & 31;
    const int gid  = lane >> 2;
    const int tig  = lane & 3;

    const int q0 = warp * 16 + gid;
    const int q1 = q0 + 8;
    const int ntv  = num_turns[b];
    const int lim0 = min(q0, ntv);
    const int lim1 = min(q1, ntv);

    uint32_t qfr[4][4];
    {
        const __nv_bfloat16* qr0 = &Q[base + (size_t)q0 * D_DIM];
        const __nv_bfloat16* qr1 = &Q[base + (size_t)q1 * D_DIM];
        #pragma unroll
        for (int kt = 0; kt < 4; kt++) {
            const int dh = kt * 16;
            qfr[kt][0] = *(const uint32_t*)&qr0[dh + 2 * tig];
            qfr[kt][1] = *(const uint32_t*)&qr1[dh + 2 * tig];
            qfr[kt][2] = *(const uint32_t*)&qr0[dh + 8 + 2 * tig];
            qfr[kt][3] = *(const uint32_t*)&qr1[dh + 8 + 2 * tig];
        }
    }
    __syncthreads();

    const int lim_max = min(warp * 16 + 15, ntv);
    const int nch = (lim_max + 63) >> 6;

    float octx[8][4];
    #pragma unroll
    for (int i = 0; i < 8; i++)
        #pragma unroll
        for (int j = 0; j < 4; j++) octx[i][j] = 0.0f;
    float m0 = -1e30f, m1 = -1e30f, l0 = 0.0f, l1 = 0.0f;

    for (int ch = 0; ch < nch; ch++) {
        const int kbase = ch * 64;

        float s[8][4];
        #pragma unroll
        for (int i = 0; i < 8; i++)
            #pragma unroll
            for (int j = 0; j < 4; j++) s[i][j] = 0.0f;

        #pragma unroll
        for (int kt = 0; kt < 4; kt++) {
            const int dh = kt * 16;
            #pragma unroll
            for (int nt8 = 0; nt8 < 8; nt8++) {
                const int krow = kbase + nt8 * 8 + gid;
                const uint32_t b0 = *(const uint32_t*)&Ks[krow * AQ_ST + dh + 2 * tig];
                const uint32_t b1 = *(const uint32_t*)&Ks[krow * AQ_ST + dh + 8 + 2 * tig];
                mma_bf16_r(s[nt8], qfr[kt][0], qfr[kt][1], qfr[kt][2],
                           qfr[kt][3], b0, b1);
            }
        }

        float mx0 = -1e30f, mx1 = -1e30f;
        #pragma unroll
        for (int i = 0; i < 8; i++) {
            const int kc = kbase + i * 8 + 2 * tig;
            s[i][0] = (kc     < lim0) ? s[i][0] * 0.125f : -1e30f;
            s[i][1] = (kc + 1 < lim0) ? s[i][1] * 0.125f : -1e30f;
            s[i][2] = (kc     < lim1) ? s[i][2] * 0.125f : -1e30f;
            s[i][3] = (kc + 1 < lim1) ? s[i][3] * 0.125f : -1e30f;
            mx0 = fmaxf(mx0, fmaxf(s[i][0], s[i][1]));
            mx1 = fmaxf(mx1, fmaxf(s[i][2], s[i][3]));
        }
        mx0 = fmaxf(mx0, __shfl_xor_sync(0xFFFFFFFFu, mx0, 1));
        mx0 = fmaxf(mx0, __shfl_xor_sync(0xFFFFFFFFu, mx0, 2));
        mx1 = fmaxf(mx1, __shfl_xor_sync(0xFFFFFFFFu, mx1, 1));
        mx1 = fmaxf(mx1, __shfl_xor_sync(0xFFFFFFFFu, mx1, 2));

        const float nm0 = fmaxf(m0, mx0);
        const float nm1 = fmaxf(m1, mx1);
        const float corr0 = __expf(m0 - nm0);
        const float corr1 = __expf(m1 - nm1);
        m0 = nm0; m1 = nm1;
        l0 *= corr0; l1 *= corr1;
        #pragma unroll
        for (int i = 0; i < 8; i++) {
            octx[i][0] *= corr0; octx[i][1] *= corr0;
            octx[i][2] *= corr1; octx[i][3] *= corr1;
        }

        #pragma unroll
        for (int i = 0; i < 8; i++) {
            const float p0 = __expf(s[i][0] - m0);
            const float p1 = __expf(s[i][1] - m0);
            const float p2 = __expf(s[i][2] - m1);
            const float p3 = __expf(s[i][3] - m1);
            l0 += p0 + p1;  l1 += p2 + p3;
            s[i][0] = p0; s[i][1] = p1; s[i][2] = p2; s[i][3] = p3;
        }

        #pragma unroll
        for (int kt16 = 0; kt16 < 4; kt16++) {
            const int i0 = 2 * kt16, i1 = i0 + 1;
            const uint32_t a0 = pack_bf2(s[i0][0], s[i0][1]);
            const uint32_t a1 = pack_bf2(s[i0][2], s[i0][3]);
            const uint32_t a2 = pack_bf2(s[i1][0], s[i1][1]);
            const uint32_t a3 = pack_bf2(s[i1][2], s[i1][3]);
            const int kb = kbase + kt16 * 16;
            #pragma unroll
            for (int ndh = 0; ndh < 8; ndh++) {
                const int vrow = ndh * 8 + gid;
                const uint32_t b0 = *(const uint32_t*)&Vt[vrow * AV_ST + kb + 2 * tig];
                const uint32_t b1 = *(const uint32_t*)&Vt[vrow * AV_ST + kb + 8 + 2 * tig];
                mma_bf16_r(octx[ndh], a0, a1, a2, a3, b0, b1);
            }
        }
    }

    l0 += __shfl_xor_sync(0xFFFFFFFFu, l0, 1);
    l0 += __shfl_xor_sync(0xFFFFFFFFu, l0, 2);
    l1 += __shfl_xor_sync(0xFFFFFFFFu, l1, 1);
    l1 += __shfl_xor_sync(0xFFFFFFFFu, l1, 2);
    const float inv0 = (lim0 > 0) ? 1.0f / l0 : 0.0f;
    const float inv1 = (lim1 > 0) ? 1.0f / l1 : 0.0f;

    __nv_bfloat16* o0 = &CTX[base + (size_t)q0 * D_DIM];
    __nv_bfloat16* o1 = &CTX[base + (size_t)q1 * D_DIM];
    #pragma unroll
    for (int ndh = 0; ndh < 8; ndh++) {
        const int c = ndh * 8 + 2 * tig;
        *(uint32_t*)&o0[c] = pack_bf2(octx[ndh][0] * inv0, octx[ndh][1] * inv0);
        *(uint32_t*)&o1[c] = pack_bf2(octx[ndh][2] * inv1, octx[ndh][3] * inv1);
    }
}

// ---------------------------------------------------------------------------
// Classifier (round 10 proven): warp per 4 rows, H + CTX fused, transposed
// conflict-free smem weights, final gather.
// ---------------------------------------------------------------------------
#define WPAD 772

__global__ __launch_bounds__(512)
void classifier_kernel(const float* __restrict__ H,
                       const __nv_bfloat16* __restrict__ CTX,
                       const float* __restrict__ Wc,
                       const float* __restrict__ bc,
                       const float* __restrict__ WoWc,
                       const float* __restrict__ boWc,
                       const int*   __restrict__ num_turns,
                       float* __restrict__ out_all,
                       float* __restrict__ out_final)
{
    __shared__ float Wtop[C_DIM * WPAD];
    __shared__ float Wbot[C_DIM * WPAD];

    for (int i = threadIdx.x; i < D_DIM * C_DIM; i += 512) {
        const int dd = i / C_DIM, cc = i % C_DIM;
        Wtop[cc * WPAD + dd] = Wc[i];
        Wbot[cc * WPAD + dd] = WoWc[i];
    }
    __syncthreads();

    const int warp = threadIdx.x >> 5;
    const int lane = threadIdx.x & 31;
    const int row0 = (blockIdx.x * 16 + warp) * 4;

    float acc[4][C_DIM];
    #pragma unroll
    for (int r = 0; r < 4; r++)
        #pragma unroll
        for (int c = 0; c < C_DIM; c++) acc[r][c] = 0.0f;

    #pragma unroll
    for (int i = 0; i < 6; i++) {
        const int off = (i * 32 + lane) * 4;
        float4 h4[4];
        #pragma unroll
        for (int r = 0; r < 4; r++)
            h4[r] = *(const float4*)&H[(size_t)(row0 + r) * D_DIM + off];
        #pragma unroll
        for (int c = 0; c < C_DIM; c++) {
            const float4 w = *(const float4*)&Wtop[c * WPAD + off];
            #pragma unroll
            for (int r = 0; r < 4; r++)
                acc[r][c] += h4[r].x * w.x + h4[r].y * w.y
                           + h4[r].z * w.z + h4[r].w * w.w;
        }
    }

    #pragma unroll
    for (int i = 0; i < 3; i++) {
        const int off = (i * 32 + lane) * 8;
        float cf[4][8];
        #pragma unroll
        for (int r = 0; r < 4; r++) {
            uint4 u = *(const uint4*)&CTX[(size_t)(row0 + r) * D_DIM + off];
            const __nv_bfloat162* hh = reinterpret_cast<const __nv_bfloat162*>(&u);
            #pragma unroll
            for (int p = 0; p < 4; p++) {
                float2 cv = __bfloat1622float2(hh[p]);
                cf[r][2*p]   = cv.x;
                cf[r][2*p+1] = cv.y;
            }
        }
        #pragma unroll
        for (int c = 0; c < C_DIM; c++) {
            const float4 w0 = *(const float4*)&Wbot[c * WPAD + off];
            const float4 w1 = *(const float4*)&Wbot[c * WPAD + off + 4];
            #pragma unroll
            for (int r = 0; r < 4; r++)
                acc[r][c] += cf[r][0] * w0.x + cf[r][1] * w0.y
                           + cf[r][2] * w0.z + cf[r][3] * w0.w
                           + cf[r][4] * w1.x + cf[r][5] * w1.y
                           + cf[r][6] * w1.z + cf[r][7] * w1.w;
        }
    }

    #pragma unroll
    for (int r = 0; r < 4; r++)
        #pragma unroll
        for (int c = 0; c < C_DIM; c++) {
            acc[r][c] += __shfl_xor_sync(0xFFFFFFFFu, acc[r][c], 16);
            acc[r][c] += __shfl_xor_sync(0xFFFFFFFFu, acc[r][c], 8);
            acc[r][c] += __shfl_xor_sync(0xFFFFFFFFu, acc[r][c], 4);
            acc[r][c] += __shfl_xor_sync(0xFFFFFFFFu, acc[r][c], 2);
            acc[r][c] += __shfl_xor_sync(0xFFFFFFFFu, acc[r][c], 1);
        }

    if (lane == 0) {
        #pragma unroll
        for (int r = 0; r < 4; r++) {
            const int row = row0 + r;
            const int t = row & (T_DIM - 1);
            const int b = row >> 8;
            float* o = &out_all[(size_t)row * C_DIM];
            const bool fin = (t == num_turns[b] - 1);
            float* f = &out_final[(size_t)b * C_DIM];
            #pragma unroll
            for (int c = 0; c < C_DIM; c++) {
                const float v = acc[r][c] + bc[c] + ((t > 0) ? boWc[c] : 0.0f);
                o[c] = v;
                if (fin) f[c] = v;
            }
        }
    }
}

// ---------------------------------------------------------------------------
// Launch
// ---------------------------------------------------------------------------
extern "C" void kernel_launch(void* const* d_in, const int* in_sizes, int n_in,
                              void* d_out, int out_size)
{
    const float* H  = (const float*)d_in[0];
    const float* Wq = (const float*)d_in[1];
    const float* bq = (const float*)d_in[2];
    const float* Wk = (const float*)d_in[3];
    const float* bk = (const float*)d_in[4];
    const float* Wv = (const float*)d_in[5];
    const float* bv = (const float*)d_in[6];
    const float* Wo = (const float*)d_in[7];
    const float* bo = (const float*)d_in[8];
    const float* Wc = (const float*)d_in[9];
    const float* bc = (const float*)d_in[10];
    const int*   nt = (const int*)  d_in[11];

    float* out_all   = (float*)d_out;
    float* out_final = (float*)d_out + (size_t)B_DIM * T_DIM * C_DIM;

    float *bp, *WoWcb, *boWcb;
    __nv_bfloat16 *Qb, *Kb, *Vb, *CTXb, *Abf, *Wbf;
    cudaGetSymbolAddress((void**)&Qb,    g_Q);
    cudaGetSymbolAddress((void**)&Kb,    g_K);
    cudaGetSymbolAddress((void**)&Vb,    g_V);
    cudaGetSymbolAddress((void**)&CTXb,  g_CTX);
    cudaGetSymbolAddress((void**)&Abf,   g_Abf);
    cudaGetSymbolAddress((void**)&Wbf,   g_Wbf);
    cudaGetSymbolAddress((void**)&bp,    g_bpack);
    cudaGetSymbolAddress((void**)&WoWcb, g_WoWc);
    cudaGetSymbolAddress((void**)&boWcb, g_boWc);

    // 1) fused prep
    prep_kernel<<<PREP_BLOCKS, 256>>>(H, Wq, Wk, Wv, bq, bk, bv, Wo, Wc, bo,
                                      Abf, Wbf, bp, WoWcb, boWcb);

    // 2) fused QKV projection (round-10 GEMM, best measured)
    cudaFuncSetAttribute(bf16_gemm_kernel,
                         cudaFuncAttributeMaxDynamicSharedMemorySize, GEMM_SMEM_BYTES);
    {
        dim3 grid(NQKV / 128, M_ROWS / 128);   // (18, 128)
        bf16_gemm_kernel<<<grid, 256, GEMM_SMEM_BYTES>>>(Abf, Wbf, bp, Qb, Kb, Vb);
    }

    // 3) bf16 flash attention v3 (Q in registers, best measured)
    cudaFuncSetAttribute(flash_attn_kernel,
                         cudaFuncAttributeMaxDynamicSharedMemorySize, ATT_SMEM_BYTES);
    flash_attn_kernel<<<B_DIM * NH_DIM, 512, ATT_SMEM_BYTES>>>(Qb, Kb, Vb, nt, CTXb);

    // 4) classifier (fused H+CTX, 4 rows/warp, best measured) + final gather
    classifier_kernel<<<M_ROWS / 64, 512>>>(H, CTXb, Wc, bc, WoWcb, boWcb,
                                            nt, out_all, out_final);
}